// round 9
// baseline (speedup 1.0000x reference)
#include <cuda_runtime.h>
#include <cuda_bf16.h>
#include <math.h>
#include <stdint.h>

#define NEG_INF (-1e30f)

// Problem constants
#define Bn 8
#define Tn 128
#define Dn 512
#define Hn 512
#define Vn 64
#define Un 32
#define Cn 65          // V + 1
#define CSTRIDE 66     // even -> conflict-free float2 LDS (checked per 16-lane phase)
#define TILE_PAD 4352  // 34*128 floats per (b,t) tile (>= 65*66=4290)
#define TILE_BYTES (TILE_PAD * 4)   // 17408
#define MROWS (Bn * Tn * Cn)        // 66560 = 520 * 128
#define NB_LOGITS (MROWS / 128)     // 520

// SMEM tile geometry for k_logits (strides in bf16 elements)
#define ASTRIDE 520
#define BSTRIDE 520
#define A_ELEMS (128 * ASTRIDE)
#define B_ELEMS (72 * BSTRIDE)
#define DYN_SMEM ((A_ELEMS + B_ELEMS) * 2)   // 208000 B
#define DSTRIDE 132

#define SCAN_SMEM (4 * TILE_BYTES)  // 69632 B ring
#define EMIN (-(1 << 28))
#define LN2F 0.69314718055994531f

// Scratch (__device__ globals; zero-initialized, 16B-aligned for vector casts)
__device__ __align__(16) float g_proj[Bn * Tn * Hn];
__device__ __align__(16) float g_den[Bn * Tn * TILE_PAD];        // [bt][k*66 + c] = exp(logit)
__device__ __align__(16) __nv_bfloat16 g_WoutT[72 * 512];

// ---------------------------------------------------------------------------
__device__ __forceinline__ float tanh_fast(float x) {
    float y; asm("tanh.approx.f32 %0, %1;" : "=f"(y) : "f"(x)); return y;
}
__device__ __forceinline__ uint32_t smem_u32(const void* p) {
    uint32_t a;
    asm("{ .reg .u64 t; cvta.to.shared.u64 t, %1; cvt.u32.u64 %0, t; }" : "=r"(a) : "l"(p));
    return a;
}
__device__ __forceinline__ void cp_async16(uint32_t saddr, const void* g) {
    asm volatile("cp.async.cg.shared.global [%0], [%1], 16;" :: "r"(saddr), "l"(g));
}
#define CP_COMMIT() asm volatile("cp.async.commit_group;" ::: "memory")
#define CP_WAIT0()  asm volatile("cp.async.wait_group 0;" ::: "memory")
#define CP_WAIT1()  asm volatile("cp.async.wait_group 1;" ::: "memory")

#define MBAR_INIT(addr, cnt) \
    asm volatile("mbarrier.init.shared.b64 [%0], %1;" :: "r"(addr), "r"((uint32_t)(cnt)) : "memory")
#define MBAR_ARRIVE(addr) \
    asm volatile("mbarrier.arrive.shared.b64 _, [%0];" :: "r"(addr) : "memory")

__device__ __forceinline__ void mbar_wait(uint32_t addr, uint32_t phase) {
    asm volatile(
        "{\n\t.reg .pred P;\n\t"
        "LW_%=:\n\t"
        "mbarrier.try_wait.parity.acquire.cta.shared::cta.b64 P, [%0], %1, 0x989680;\n\t"
        "@P bra.uni LD_%=;\n\t"
        "bra.uni LW_%=;\n\t"
        "LD_%=:\n\t}"
        :: "r"(addr), "r"(phase) : "memory");
}

__device__ __forceinline__ void mma16816(float* c, const uint32_t* a, const uint32_t* b) {
    asm volatile(
        "mma.sync.aligned.m16n8k16.row.col.f32.bf16.bf16.f32 "
        "{%0,%1,%2,%3}, {%4,%5,%6,%7}, {%8,%9}, {%0,%1,%2,%3};"
        : "+f"(c[0]), "+f"(c[1]), "+f"(c[2]), "+f"(c[3])
        : "r"(a[0]), "r"(a[1]), "r"(a[2]), "r"(a[3]), "r"(b[0]), "r"(b[1]));
}
__device__ __forceinline__ uint32_t to_tf32(float f) {
    uint32_t u; asm("cvt.rna.tf32.f32 %0, %1;" : "=r"(u) : "f"(f)); return u;
}
__device__ __forceinline__ void mma_tf32(float* c, const uint32_t* a, const uint32_t* b) {
    asm volatile(
        "mma.sync.aligned.m16n8k8.row.col.f32.tf32.tf32.f32 "
        "{%0,%1,%2,%3}, {%4,%5,%6,%7}, {%8,%9}, {%0,%1,%2,%3};"
        : "+f"(c[0]), "+f"(c[1]), "+f"(c[2]), "+f"(c[3])
        : "r"(a[0]), "r"(a[1]), "r"(a[2]), "r"(a[3]), "r"(b[0]), "r"(b[1]));
}

// 2^d for d in [-127, 127], exact, branchless
__device__ __forceinline__ float exp2i(int d) {
    return __int_as_float((d + 127) << 23);
}
// (m,e) <- own*2^eo + oth*2^ep, with own,oth >= 0; m in [1,2) or 0.
__device__ __forceinline__ void accum2(float own, int eo, float oth, int ep,
                                       float& m, int& e) {
    int base = (eo > ep) ? eo : ep;
    int d0 = eo - base; d0 = (d0 < -127) ? -127 : d0;
    int d1 = ep - base; d1 = (d1 < -127) ? -127 : d1;
    float nn = own * exp2i(d0) + oth * exp2i(d1);
    if (nn > 0.f) {
        int bits = __float_as_int(nn);
        e = base + ((bits >> 23) & 0xFF) - 127;
        m = __int_as_float((bits & 0x007FFFFF) | 0x3F800000);
    } else {
        m = 0.f; e = EMIN;
    }
}

// ---------------------------------------------------------------------------
// Kernel 0: transpose + bf16-convert Wout -> g_WoutT[n][k]  (rows n>=65 zero)
// ---------------------------------------------------------------------------
__global__ void k_prep(const float* __restrict__ Wo) {
    const int tid = threadIdx.x + blockIdx.x * blockDim.x;
    for (int e = tid; e < 72 * 512; e += blockDim.x * gridDim.x) {
        int n = e >> 9;
        int k = e & 511;
        float v = (n < Cn) ? Wo[k * Cn + n] : 0.f;
        g_WoutT[e] = __float2bfloat16(v);
    }
}

// ---------------------------------------------------------------------------
// Kernel 1: proj = frames @ W_frame via tf32 mma.sync (m16n8k8).
// Double buffer with wait_group 1 so compute(ch) overlaps flight(ch+1).
// ---------------------------------------------------------------------------
#define PAS 36

__global__ __launch_bounds__(128) void k_proj(const float* __restrict__ A,
                                              const float* __restrict__ Bm) {
    __shared__ __align__(16) float As2[2][64 * PAS];
    __shared__ __align__(16) float Bs2[2][32 * PAS];

    const int tid = threadIdx.x;
    const int wid = tid >> 5;
    const int lane = tid & 31;
    const int gq = lane >> 2;
    const int tg = lane & 3;
    const int bm = blockIdx.y * 64;
    const int bn = blockIdx.x * 32;
    const int wm = (wid >> 1) * 32;
    const int wn = (wid & 1) * 16;

    const uint32_t asb[2] = { smem_u32(As2[0]), smem_u32(As2[1]) };
    const uint32_t bsb[2] = { smem_u32(Bs2[0]), smem_u32(Bs2[1]) };

    auto issue = [&](int ch, int buf) {
        const int kc = ch * 32;
#pragma unroll
        for (int l = 0; l < 4; l++) {
            int o = tid + l * 128;
            int row = o >> 3, seg = o & 7;
            cp_async16(asb[buf] + (row * PAS + seg * 4) * 4,
                       A + (size_t)(bm + row) * Dn + kc + seg * 4);
        }
#pragma unroll
        for (int l = 0; l < 2; l++) {
            int o = tid + l * 128;
            int kr = o >> 3, seg = o & 7;
            cp_async16(bsb[buf] + (kr * PAS + seg * 4) * 4,
                       Bm + (size_t)(kc + kr) * Hn + bn + seg * 4);
        }
        CP_COMMIT();
    };

    float acc[2][2][4];
#pragma unroll
    for (int mt = 0; mt < 2; mt++)
#pragma unroll
        for (int nt = 0; nt < 2; nt++)
#pragma unroll
            for (int i = 0; i < 4; i++) acc[mt][nt][i] = 0.f;

    issue(0, 0);

    for (int ch = 0; ch < 16; ch++) {
        const int buf = ch & 1;
        if (ch + 1 < 16) { issue(ch + 1, 1 - buf); CP_WAIT1(); }
        else             { CP_WAIT0(); }
        __syncthreads();

        const float* As = As2[buf];
        const float* Bs = Bs2[buf];
#pragma unroll
        for (int ks = 0; ks < 4; ks++) {
            const int k0 = ks * 8;
            uint32_t bf[2][2];
#pragma unroll
            for (int nt = 0; nt < 2; nt++) {
                int cb = wn + nt * 8 + gq;
                bf[nt][0] = to_tf32(Bs[(k0 + tg) * PAS + cb]);
                bf[nt][1] = to_tf32(Bs[(k0 + tg + 4) * PAS + cb]);
            }
#pragma unroll
            for (int mt = 0; mt < 2; mt++) {
                int rm = wm + mt * 16 + gq;
                uint32_t af[4];
                af[0] = to_tf32(As[rm * PAS + k0 + tg]);
                af[1] = to_tf32(As[(rm + 8) * PAS + k0 + tg]);
                af[2] = to_tf32(As[rm * PAS + k0 + tg + 4]);
                af[3] = to_tf32(As[(rm + 8) * PAS + k0 + tg + 4]);
#pragma unroll
                for (int nt = 0; nt < 2; nt++) mma_tf32(acc[mt][nt], af, bf[nt]);
            }
        }
        __syncthreads();   // all done reading buf before it is re-issued
    }

#pragma unroll
    for (int mt = 0; mt < 2; mt++) {
        int row = bm + wm + mt * 16 + gq;
#pragma unroll
        for (int nt = 0; nt < 2; nt++) {
            int col = bn + wn + nt * 8 + tg * 2;
            *reinterpret_cast<float2*>(&g_proj[(size_t)row * Hn + col]) =
                make_float2(acc[mt][nt][0], acc[mt][nt][1]);
            *reinterpret_cast<float2*>(&g_proj[(size_t)(row + 8) * Hn + col]) =
                make_float2(acc[mt][nt][2], acc[mt][nt][3]);
        }
    }
}

// ---------------------------------------------------------------------------
// Kernel 2: logits via mma.sync bf16 (m16n8k16), 256 threads (8 warps).
// Stores EXP of all logits transposed into g_den[bt][k*66 + c].
// ---------------------------------------------------------------------------
__global__ __launch_bounds__(256) void k_logits(const float* __restrict__ ce) {
    extern __shared__ __align__(16) __nv_bfloat16 dynsmem[];
    __nv_bfloat16* Asm = dynsmem;
    __nv_bfloat16* Bsm = dynsmem + A_ELEMS;
    __shared__ __align__(16) float p[3 * 512];
    __shared__ int btc[128];

    const int tid = threadIdx.x;
    const int wid = tid >> 5;
    const int lane = tid & 31;
    const int gq = lane >> 2;
    const int tg = lane & 3;
    const int g0 = blockIdx.x * 128;
    const int bt0 = g0 / 65;

    for (int i = tid; i < 3 * 512; i += 256) {
        int bt = bt0 + (i >> 9);
        p[i] = (bt < Bn * Tn) ? g_proj[(size_t)bt * Hn + (i & 511)] : 0.f;
    }
    for (int e = tid; e < 72 * 64; e += 256) {
        int n = e >> 6, kq = e & 63;
        *reinterpret_cast<uint4*>(&Bsm[n * BSTRIDE + kq * 8]) =
            *reinterpret_cast<const uint4*>(&g_WoutT[n * 512 + kq * 8]);
    }
    if (tid < 128) {
        int bt = (g0 + tid) / 65;
        btc[tid] = bt * TILE_PAD + (g0 + tid - bt * 65);
    }
    __syncthreads();

    {
        const int half = tid >> 7;
        const int col = (tid & 127) * 4;
        int g = g0 + half * 64;
        int bt = g / 65;
        int c = g - bt * 65;
#pragma unroll 4
        for (int rr = 0; rr < 64; rr++) {
            int r = half * 64 + rr;
            int pb = bt - bt0;
            float4 pe = *reinterpret_cast<const float4*>(&p[pb * 512 + col]);
            float4 cv = *reinterpret_cast<const float4*>(&ce[(size_t)c * Hn + col]);
            __nv_bfloat162 b0 = __floats2bfloat162_rn(tanh_fast(pe.x + cv.x),
                                                      tanh_fast(pe.y + cv.y));
            __nv_bfloat162 b1 = __floats2bfloat162_rn(tanh_fast(pe.z + cv.z),
                                                      tanh_fast(pe.w + cv.w));
            uint2 pk = make_uint2(*reinterpret_cast<uint32_t*>(&b0),
                                  *reinterpret_cast<uint32_t*>(&b1));
            *reinterpret_cast<uint2*>(&Asm[r * ASTRIDE + col]) = pk;
            if (++c == 65) { c = 0; ++bt; }
        }
    }
    __syncthreads();

    float acc[9][4];
#pragma unroll
    for (int nt = 0; nt < 9; nt++)
#pragma unroll
        for (int i = 0; i < 4; i++) acc[nt][i] = 0.f;

    const int wbase = wid * 16;
#pragma unroll 2
    for (int kk = 0; kk < 32; kk++) {
        const int k0 = kk * 16;
        uint32_t bf[9][2];
#pragma unroll
        for (int nt = 0; nt < 9; nt++) {
            int n = nt * 8 + gq;
            bf[nt][0] = *reinterpret_cast<const uint32_t*>(&Bsm[n * BSTRIDE + k0 + tg * 2]);
            bf[nt][1] = *reinterpret_cast<const uint32_t*>(&Bsm[n * BSTRIDE + k0 + 8 + tg * 2]);
        }
        const int r0 = wbase + gq;
        uint32_t af[4];
        af[0] = *reinterpret_cast<const uint32_t*>(&Asm[r0 * ASTRIDE + k0 + tg * 2]);
        af[1] = *reinterpret_cast<const uint32_t*>(&Asm[(r0 + 8) * ASTRIDE + k0 + tg * 2]);
        af[2] = *reinterpret_cast<const uint32_t*>(&Asm[r0 * ASTRIDE + k0 + 8 + tg * 2]);
        af[3] = *reinterpret_cast<const uint32_t*>(&Asm[(r0 + 8) * ASTRIDE + k0 + 8 + tg * 2]);
#pragma unroll
        for (int nt = 0; nt < 9; nt++) mma16816(acc[nt], af, bf[nt]);
    }
    __syncthreads();

    float* d_sm = reinterpret_cast<float*>(dynsmem);
    {
        const int r0 = wbase + gq;
#pragma unroll
        for (int nt = 0; nt < 9; nt++) {
            const int col = nt * 8 + tg * 2;
            d_sm[col * DSTRIDE + r0]           = acc[nt][0];
            d_sm[(col + 1) * DSTRIDE + r0]     = acc[nt][1];
            d_sm[col * DSTRIDE + r0 + 8]       = acc[nt][2];
            d_sm[(col + 1) * DSTRIDE + r0 + 8] = acc[nt][3];
        }
    }
    __syncthreads();

    for (int e = tid; e < Cn * 128; e += 256) {
        int k = e >> 7;
        int r = e & 127;
        g_den[(size_t)btc[r] + k * CSTRIDE] = __expf(d_sm[k * DSTRIDE + r]);
    }
}

// ---------------------------------------------------------------------------
// Kernel 3: warp-specialized scan, 224 threads, one block per batch.
//  w0: den states 1..32 (lane v -> v+1)
//  w1: den states 33..64 (lane v -> v+33); lane 31 also state 0
//  w2: numerator, 33 states, reads GLOBAL directly (distance-4 reg ring),
//      completely outside the mbarrier pipeline
//  w3-6: producers (slot = wid-3), cp.async ring depth 4, empty count = 2
// Renorm every 4 steps is BARRIER-FREE: both den warps compute the identical
// max from the beta vector they read anyway in the matvec.
// One bar.sync(1,64) per step is the only inter-warp sync on the den path.
// ---------------------------------------------------------------------------
__global__ __launch_bounds__(224) void k_scan(const int* __restrict__ num_frames,
                                              const int* __restrict__ labels,
                                              const int* __restrict__ num_labels,
                                              float* __restrict__ out) {
    extern __shared__ __align__(16) float tilebuf[];   // 4 * TILE_PAD floats
    __shared__ __align__(16) float beta_sh[2][68];
    __shared__ float nm_fin[Un + 1];
    __shared__ int ne_fin[Un + 1];
    __shared__ int esum_sh;
    __shared__ __align__(8) unsigned long long mbars[8];   // full[0..3], empty[4..7]

    const int b = blockIdx.x;
    const int tid = threadIdx.x;
    const int wid = tid >> 5;
    const int lane = tid & 31;
    const int Tb = num_frames[b];          // in [64, 128]

    uint32_t mb_full[4], mb_empty[4];
#pragma unroll
    for (int s = 0; s < 4; s++) {
        mb_full[s] = smem_u32(&mbars[s]);
        mb_empty[s] = smem_u32(&mbars[4 + s]);
    }
    if (tid == 0) {
#pragma unroll
        for (int s = 0; s < 4; s++) {
            MBAR_INIT(mb_full[s], 32);     // 32 producer-thread arrivals
            MBAR_INIT(mb_empty[s], 2);     // 2 den-warp elected arrivals
        }
    }
    if (wid < 2) {
        beta_sh[0][wid * 32 + lane + 1] = 0.f;
        if (tid == 31) beta_sh[0][0] = 1.f;
    }
    __syncthreads();

    const float* base = g_den + (size_t)(b * Tn) * TILE_PAD;

    if (wid >= 3) {
        // ---- producer warp: slot p = wid-3, tiles t = p, p+4, ...
        const int p = wid - 3;
        const uint32_t dst0 = smem_u32(tilebuf) + p * TILE_BYTES;
        int eph = 1;
        for (int t = p; t < Tb; t += 4) {
            mbar_wait(mb_empty[p], (uint32_t)eph);
            eph ^= 1;
            const float* src = base + (size_t)t * TILE_PAD;
#pragma unroll
            for (int i = lane; i < TILE_PAD / 4; i += 32)
                cp_async16(dst0 + i * 16, src + i * 4);
            CP_COMMIT();
            CP_WAIT0();
            MBAR_ARRIVE(mb_full[p]);
        }
    } else if (wid < 2) {
        // ---- denominator: lane -> state row = wid*32 + lane + 1
        const int row = wid * 32 + lane + 1;
        const bool ex = (tid == 31);       // w0 lane31? NO: state 0 on w1 lane31
        const bool ex0 = (wid == 1 && lane == 31);
        const int rowoff = row * CSTRIDE;
        float av = 0.f;
        float av0 = ex0 ? 1.f : 0.f;
        int esum = 0;
        (void)ex;

        for (int t = 0; t < Tb; t++) {
            const int s = t & 3;
            mbar_wait(mb_full[s], (uint32_t)((t >> 2) & 1));
            const float* Tt = tilebuf + s * TILE_PAD;
            const float* bsh = beta_sh[t & 1];
            const float2* r2 = reinterpret_cast<const float2*>(Tt + rowoff);
            const float2* b2 = reinterpret_cast<const float2*>(bsh);
            const bool rn = ((t & 3) == 3);

            float s0 = 0.f, s1 = 0.f, s2 = 0.f, s3 = 0.f;
            float mx = bsh[64];
#pragma unroll 8
            for (int c2 = 0; c2 < 32; c2 += 2) {
                float2 a0 = r2[c2],     w0v = b2[c2];
                float2 a1 = r2[c2 + 1], w1v = b2[c2 + 1];
                s0 += a0.x * w0v.x; s1 += a0.y * w0v.y;
                s2 += a1.x * w1v.x; s3 += a1.y * w1v.y;
                if (rn) {
                    mx = fmaxf(mx, fmaxf(fmaxf(w0v.x, w0v.y), fmaxf(w1v.x, w1v.y)));
                }
            }
            float mv = (s0 + s1) + (s2 + s3) + r2[32].x * bsh[64];
            float nv = fmaf(av, Tt[row], mv);       // stay: beta[row]*blank[row]
            float nv0 = ex0 ? av0 * Tt[0] : 0.f;

            if (lane == 0) MBAR_ARRIVE(mb_empty[s]);   // warp done reading tile

            if (rn) {
                // identical on every den thread: max of previous beta vector
                int eb = ((__float_as_int(mx) >> 23) & 0xFF) - 127;
                float sc = exp2i(-eb);
                nv *= sc; nv0 *= sc; esum += eb;
            }

            beta_sh[1 - (t & 1)][row] = nv;
            if (ex0) beta_sh[1 - (t & 1)][0] = nv0;
            av = nv; av0 = nv0;
            asm volatile("bar.sync 1, 64;" ::: "memory");
        }
        if (tid == 0) esum_sh = esum;
    } else {
        // ---- numerator (warp 2): lane j = state j; lane 31 also state 32.
        // Reads needed values straight from GLOBAL with a distance-4 ring.
        const int* lb = labels + b * Un;
        const int j = lane;
        const int cj = (j == 0) ? 0 : lb[j - 1];
        const int cm = (j >= 2) ? lb[j - 2] : 0;
        const int c32 = lb[31], c31 = lb[30];
        const bool l31 = (lane == 31);

        float m = (j == 0) ? 1.f : 0.f;
        int e = (j == 0) ? 0 : EMIN;
        float m2 = 0.f;             // state 32 (lane 31)
        int e2 = EMIN;

        // ring of prefetched values
        float rA[4], rB[4], rC[4], rD[4];
        const float* gA = base + cj;                        // blank at ctx j
        const float* gB = base + cj * CSTRIDE + cm;         // lex into ctx j
        const float* gC = base + c32;                       // blank at ctx 32
        const float* gD = base + c32 * CSTRIDE + c31;       // lex into ctx 32
#pragma unroll
        for (int s = 0; s < 4; s++) {
            rA[s] = gA[s * TILE_PAD];
            rB[s] = (j > 0) ? gB[s * TILE_PAD] : 0.f;
            rC[s] = l31 ? gC[s * TILE_PAD] : 0.f;
            rD[s] = l31 ? gD[s * TILE_PAD] : 0.f;
        }

        for (int t = 0; t < Tb; t++) {
            const int s = t & 3;
            float vA = rA[s], vB = rB[s], vC = rC[s], vD = rD[s];
            if (t + 4 < Tb) {
                size_t o = (size_t)(t + 4) * TILE_PAD;
                rA[s] = gA[o];
                if (j > 0) rB[s] = gB[o];
                if (l31) { rC[s] = gC[o]; rD[s] = gD[o]; }
            }

            float mp = __shfl_up_sync(0xffffffffu, m, 1);
            int epv = __shfl_up_sync(0xffffffffu, e, 1);
            float mprev = m; int eprev = e;          // lane31: state 31 pre-update

            float own = m * vA;
            float oth = (j > 0) ? mp * vB : 0.f;
            int epo = (j > 0) ? epv : EMIN;
            accum2(own, e, oth, epo, m, e);

            if (l31) {
                float own2 = m2 * vC;
                float oth2 = mprev * vD;
                accum2(own2, e2, oth2, eprev, m2, e2);
            }
        }
        nm_fin[j] = m;
        ne_fin[j] = e;
        if (l31) { nm_fin[32] = m2; ne_fin[32] = e2; }
    }

    __syncthreads();
    if (tid == 0) {
        const float* bf = beta_sh[Tb & 1];
        float ssum = 0.f;
        for (int c = 0; c < Cn; c++) ssum += bf[c];
        float den = (float)esum_sh * LN2F + __logf(ssum);
        int nl = num_labels[b];
        float num = __logf(nm_fin[nl]) + (float)ne_fin[nl] * LN2F;
        out[b] = den - num;
    }
}

// ---------------------------------------------------------------------------
extern "C" void kernel_launch(void* const* d_in, const int* in_sizes, int n_in,
                              void* d_out, int out_size) {
    const float* frames = (const float*)d_in[0];   // (8,128,512)
    const float* Wf     = (const float*)d_in[1];   // (512,512)
    const float* ce     = (const float*)d_in[2];   // (65,512)
    const float* Wo     = (const float*)d_in[3];   // (512,65)
    const int* nf       = (const int*)d_in[4];     // (8,)
    const int* labels   = (const int*)d_in[5];     // (8,32)
    const int* nl       = (const int*)d_in[6];     // (8,)
    float* out = (float*)d_out;                    // (8,)

    cudaFuncSetAttribute(k_logits, cudaFuncAttributeMaxDynamicSharedMemorySize, DYN_SMEM);
    cudaFuncSetAttribute(k_scan, cudaFuncAttributeMaxDynamicSharedMemorySize, SCAN_SMEM);

    k_prep<<<4, 256>>>(Wo);
    k_proj<<<dim3(Hn / 32, (Bn * Tn) / 64), 128>>>(frames, Wf);
    k_logits<<<NB_LOGITS, 256, DYN_SMEM>>>(ce);
    k_scan<<<Bn, 224, SCAN_SMEM>>>(nf, labels, nl, out);
}

// round 10
// speedup vs baseline: 1.2214x; 1.2214x over previous
#include <cuda_runtime.h>
#include <cuda_bf16.h>
#include <math.h>
#include <stdint.h>

#define NEG_INF (-1e30f)

// Problem constants
#define Bn 8
#define Tn 128
#define Dn 512
#define Hn 512
#define Vn 64
#define Un 32
#define Cn 65          // V + 1
#define CSTRIDE 67     // odd -> conflict-free scalar LDS in scan
#define TILE_PAD 4480  // 35*128 floats per (b,t) tile (>= 65*67=4355)
#define TILE_BYTES (TILE_PAD * 4)   // 17920
#define MROWS (Bn * Tn * Cn)        // 66560 = 520 * 128
#define NB_LOGITS (MROWS / 128)     // 520

// SMEM tile geometry for k_logits (strides in bf16 elements)
#define ASTRIDE 520
#define BSTRIDE 520
#define A_ELEMS (128 * ASTRIDE)
#define B_ELEMS (72 * BSTRIDE)
#define DYN_SMEM ((A_ELEMS + B_ELEMS) * 2)   // 208000 B
#define DSTRIDE 132

#define SCAN_SMEM (4 * TILE_BYTES)  // 71680 B ring
#define EMIN (-(1 << 28))
#define LN2F 0.69314718055994531f

// Scratch (__device__ globals; zero-initialized, 16B-aligned for vector casts)
__device__ __align__(16) float g_proj[Bn * Tn * Hn];
__device__ __align__(16) float g_den[Bn * Tn * TILE_PAD];        // [bt][k*67 + c] = exp(logit)
__device__ __align__(16) __nv_bfloat16 g_WoutT[72 * 512];

// ---------------------------------------------------------------------------
__device__ __forceinline__ float tanh_fast(float x) {
    float y; asm("tanh.approx.f32 %0, %1;" : "=f"(y) : "f"(x)); return y;
}
__device__ __forceinline__ uint32_t smem_u32(const void* p) {
    uint32_t a;
    asm("{ .reg .u64 t; cvta.to.shared.u64 t, %1; cvt.u32.u64 %0, t; }" : "=r"(a) : "l"(p));
    return a;
}
__device__ __forceinline__ void cp_async16(uint32_t saddr, const void* g) {
    asm volatile("cp.async.cg.shared.global [%0], [%1], 16;" :: "r"(saddr), "l"(g));
}
#define CP_COMMIT() asm volatile("cp.async.commit_group;" ::: "memory")
#define CP_WAIT0()  asm volatile("cp.async.wait_group 0;" ::: "memory")
#define CP_WAIT1()  asm volatile("cp.async.wait_group 1;" ::: "memory")

#define MBAR_INIT(addr, cnt) \
    asm volatile("mbarrier.init.shared.b64 [%0], %1;" :: "r"(addr), "r"((uint32_t)(cnt)) : "memory")
#define MBAR_ARRIVE(addr) \
    asm volatile("mbarrier.arrive.shared.b64 _, [%0];" :: "r"(addr) : "memory")

__device__ __forceinline__ void mbar_wait(uint32_t addr, uint32_t phase) {
    asm volatile(
        "{\n\t.reg .pred P;\n\t"
        "LW_%=:\n\t"
        "mbarrier.try_wait.parity.acquire.cta.shared::cta.b64 P, [%0], %1, 0x989680;\n\t"
        "@P bra.uni LD_%=;\n\t"
        "bra.uni LW_%=;\n\t"
        "LD_%=:\n\t}"
        :: "r"(addr), "r"(phase) : "memory");
}

__device__ __forceinline__ void mma16816(float* c, const uint32_t* a, const uint32_t* b) {
    asm volatile(
        "mma.sync.aligned.m16n8k16.row.col.f32.bf16.bf16.f32 "
        "{%0,%1,%2,%3}, {%4,%5,%6,%7}, {%8,%9}, {%0,%1,%2,%3};"
        : "+f"(c[0]), "+f"(c[1]), "+f"(c[2]), "+f"(c[3])
        : "r"(a[0]), "r"(a[1]), "r"(a[2]), "r"(a[3]), "r"(b[0]), "r"(b[1]));
}
__device__ __forceinline__ uint32_t to_tf32(float f) {
    uint32_t u; asm("cvt.rna.tf32.f32 %0, %1;" : "=r"(u) : "f"(f)); return u;
}
__device__ __forceinline__ void mma_tf32(float* c, const uint32_t* a, const uint32_t* b) {
    asm volatile(
        "mma.sync.aligned.m16n8k8.row.col.f32.tf32.tf32.f32 "
        "{%0,%1,%2,%3}, {%4,%5,%6,%7}, {%8,%9}, {%0,%1,%2,%3};"
        : "+f"(c[0]), "+f"(c[1]), "+f"(c[2]), "+f"(c[3])
        : "r"(a[0]), "r"(a[1]), "r"(a[2]), "r"(a[3]), "r"(b[0]), "r"(b[1]));
}

// 2^d for d in [-127, 127], exact, branchless
__device__ __forceinline__ float exp2i(int d) {
    return __int_as_float((d + 127) << 23);
}
// (m,e) <- own*2^eo + oth*2^ep, with own,oth >= 0; m in [1,2) or 0.
__device__ __forceinline__ void accum2(float own, int eo, float oth, int ep,
                                       float& m, int& e) {
    int base = (eo > ep) ? eo : ep;
    int d0 = eo - base; d0 = (d0 < -127) ? -127 : d0;
    int d1 = ep - base; d1 = (d1 < -127) ? -127 : d1;
    float nn = own * exp2i(d0) + oth * exp2i(d1);
    if (nn > 0.f) {
        int bits = __float_as_int(nn);
        e = base + ((bits >> 23) & 0xFF) - 127;
        m = __int_as_float((bits & 0x007FFFFF) | 0x3F800000);
    } else {
        m = 0.f; e = EMIN;
    }
}

// ---------------------------------------------------------------------------
// Kernel 0: transpose + bf16-convert Wout -> g_WoutT[n][k]  (rows n>=65 zero)
// ---------------------------------------------------------------------------
__global__ void k_prep(const float* __restrict__ Wo) {
    const int tid = threadIdx.x + blockIdx.x * blockDim.x;
    for (int e = tid; e < 72 * 512; e += blockDim.x * gridDim.x) {
        int n = e >> 9;
        int k = e & 511;
        float v = (n < Cn) ? Wo[k * Cn + n] : 0.f;
        g_WoutT[e] = __float2bfloat16(v);
    }
}

// ---------------------------------------------------------------------------
// Kernel 1: proj = frames @ W_frame via tf32 mma.sync (m16n8k8).
// Double buffer with wait_group 1 so compute(ch) overlaps flight(ch+1).
// ---------------------------------------------------------------------------
#define PAS 36

__global__ __launch_bounds__(128) void k_proj(const float* __restrict__ A,
                                              const float* __restrict__ Bm) {
    __shared__ __align__(16) float As2[2][64 * PAS];
    __shared__ __align__(16) float Bs2[2][32 * PAS];

    const int tid = threadIdx.x;
    const int wid = tid >> 5;
    const int lane = tid & 31;
    const int gq = lane >> 2;
    const int tg = lane & 3;
    const int bm = blockIdx.y * 64;
    const int bn = blockIdx.x * 32;
    const int wm = (wid >> 1) * 32;
    const int wn = (wid & 1) * 16;

    const uint32_t asb[2] = { smem_u32(As2[0]), smem_u32(As2[1]) };
    const uint32_t bsb[2] = { smem_u32(Bs2[0]), smem_u32(Bs2[1]) };

    auto issue = [&](int ch, int buf) {
        const int kc = ch * 32;
#pragma unroll
        for (int l = 0; l < 4; l++) {
            int o = tid + l * 128;
            int row = o >> 3, seg = o & 7;
            cp_async16(asb[buf] + (row * PAS + seg * 4) * 4,
                       A + (size_t)(bm + row) * Dn + kc + seg * 4);
        }
#pragma unroll
        for (int l = 0; l < 2; l++) {
            int o = tid + l * 128;
            int kr = o >> 3, seg = o & 7;
            cp_async16(bsb[buf] + (kr * PAS + seg * 4) * 4,
                       Bm + (size_t)(kc + kr) * Hn + bn + seg * 4);
        }
        CP_COMMIT();
    };

    float acc[2][2][4];
#pragma unroll
    for (int mt = 0; mt < 2; mt++)
#pragma unroll
        for (int nt = 0; nt < 2; nt++)
#pragma unroll
            for (int i = 0; i < 4; i++) acc[mt][nt][i] = 0.f;

    issue(0, 0);

    for (int ch = 0; ch < 16; ch++) {
        const int buf = ch & 1;
        if (ch + 1 < 16) { issue(ch + 1, 1 - buf); CP_WAIT1(); }
        else             { CP_WAIT0(); }
        __syncthreads();

        const float* As = As2[buf];
        const float* Bs = Bs2[buf];
#pragma unroll
        for (int ks = 0; ks < 4; ks++) {
            const int k0 = ks * 8;
            uint32_t bf[2][2];
#pragma unroll
            for (int nt = 0; nt < 2; nt++) {
                int cb = wn + nt * 8 + gq;
                bf[nt][0] = to_tf32(Bs[(k0 + tg) * PAS + cb]);
                bf[nt][1] = to_tf32(Bs[(k0 + tg + 4) * PAS + cb]);
            }
#pragma unroll
            for (int mt = 0; mt < 2; mt++) {
                int rm = wm + mt * 16 + gq;
                uint32_t af[4];
                af[0] = to_tf32(As[rm * PAS + k0 + tg]);
                af[1] = to_tf32(As[(rm + 8) * PAS + k0 + tg]);
                af[2] = to_tf32(As[rm * PAS + k0 + tg + 4]);
                af[3] = to_tf32(As[(rm + 8) * PAS + k0 + tg + 4]);
#pragma unroll
                for (int nt = 0; nt < 2; nt++) mma_tf32(acc[mt][nt], af, bf[nt]);
            }
        }
        __syncthreads();   // all done reading buf before it is re-issued
    }

#pragma unroll
    for (int mt = 0; mt < 2; mt++) {
        int row = bm + wm + mt * 16 + gq;
#pragma unroll
        for (int nt = 0; nt < 2; nt++) {
            int col = bn + wn + nt * 8 + tg * 2;
            *reinterpret_cast<float2*>(&g_proj[(size_t)row * Hn + col]) =
                make_float2(acc[mt][nt][0], acc[mt][nt][1]);
            *reinterpret_cast<float2*>(&g_proj[(size_t)(row + 8) * Hn + col]) =
                make_float2(acc[mt][nt][2], acc[mt][nt][3]);
        }
    }
}

// ---------------------------------------------------------------------------
// Kernel 2: logits via mma.sync bf16 (m16n8k16), 256 threads (8 warps).
// Stores EXP of all logits transposed into g_den[bt][k*67 + c].
// ---------------------------------------------------------------------------
__global__ __launch_bounds__(256) void k_logits(const float* __restrict__ ce) {
    extern __shared__ __align__(16) __nv_bfloat16 dynsmem[];
    __nv_bfloat16* Asm = dynsmem;
    __nv_bfloat16* Bsm = dynsmem + A_ELEMS;
    __shared__ __align__(16) float p[3 * 512];
    __shared__ int btc[128];

    const int tid = threadIdx.x;
    const int wid = tid >> 5;
    const int lane = tid & 31;
    const int gq = lane >> 2;
    const int tg = lane & 3;
    const int g0 = blockIdx.x * 128;
    const int bt0 = g0 / 65;

    for (int i = tid; i < 3 * 512; i += 256) {
        int bt = bt0 + (i >> 9);
        p[i] = (bt < Bn * Tn) ? g_proj[(size_t)bt * Hn + (i & 511)] : 0.f;
    }
    for (int e = tid; e < 72 * 64; e += 256) {
        int n = e >> 6, kq = e & 63;
        *reinterpret_cast<uint4*>(&Bsm[n * BSTRIDE + kq * 8]) =
            *reinterpret_cast<const uint4*>(&g_WoutT[n * 512 + kq * 8]);
    }
    if (tid < 128) {
        int bt = (g0 + tid) / 65;
        btc[tid] = bt * TILE_PAD + (g0 + tid - bt * 65);
    }
    __syncthreads();

    {
        const int half = tid >> 7;
        const int col = (tid & 127) * 4;
        int g = g0 + half * 64;
        int bt = g / 65;
        int c = g - bt * 65;
#pragma unroll 4
        for (int rr = 0; rr < 64; rr++) {
            int r = half * 64 + rr;
            int pb = bt - bt0;
            float4 pe = *reinterpret_cast<const float4*>(&p[pb * 512 + col]);
            float4 cv = *reinterpret_cast<const float4*>(&ce[(size_t)c * Hn + col]);
            __nv_bfloat162 b0 = __floats2bfloat162_rn(tanh_fast(pe.x + cv.x),
                                                      tanh_fast(pe.y + cv.y));
            __nv_bfloat162 b1 = __floats2bfloat162_rn(tanh_fast(pe.z + cv.z),
                                                      tanh_fast(pe.w + cv.w));
            uint2 pk = make_uint2(*reinterpret_cast<uint32_t*>(&b0),
                                  *reinterpret_cast<uint32_t*>(&b1));
            *reinterpret_cast<uint2*>(&Asm[r * ASTRIDE + col]) = pk;
            if (++c == 65) { c = 0; ++bt; }
        }
    }
    __syncthreads();

    float acc[9][4];
#pragma unroll
    for (int nt = 0; nt < 9; nt++)
#pragma unroll
        for (int i = 0; i < 4; i++) acc[nt][i] = 0.f;

    const int wbase = wid * 16;
#pragma unroll 2
    for (int kk = 0; kk < 32; kk++) {
        const int k0 = kk * 16;
        uint32_t bf[9][2];
#pragma unroll
        for (int nt = 0; nt < 9; nt++) {
            int n = nt * 8 + gq;
            bf[nt][0] = *reinterpret_cast<const uint32_t*>(&Bsm[n * BSTRIDE + k0 + tg * 2]);
            bf[nt][1] = *reinterpret_cast<const uint32_t*>(&Bsm[n * BSTRIDE + k0 + 8 + tg * 2]);
        }
        const int r0 = wbase + gq;
        uint32_t af[4];
        af[0] = *reinterpret_cast<const uint32_t*>(&Asm[r0 * ASTRIDE + k0 + tg * 2]);
        af[1] = *reinterpret_cast<const uint32_t*>(&Asm[(r0 + 8) * ASTRIDE + k0 + tg * 2]);
        af[2] = *reinterpret_cast<const uint32_t*>(&Asm[r0 * ASTRIDE + k0 + 8 + tg * 2]);
        af[3] = *reinterpret_cast<const uint32_t*>(&Asm[(r0 + 8) * ASTRIDE + k0 + 8 + tg * 2]);
#pragma unroll
        for (int nt = 0; nt < 9; nt++) mma16816(acc[nt], af, bf[nt]);
    }
    __syncthreads();

    float* d_sm = reinterpret_cast<float*>(dynsmem);
    {
        const int r0 = wbase + gq;
#pragma unroll
        for (int nt = 0; nt < 9; nt++) {
            const int col = nt * 8 + tg * 2;
            d_sm[col * DSTRIDE + r0]           = acc[nt][0];
            d_sm[(col + 1) * DSTRIDE + r0]     = acc[nt][1];
            d_sm[col * DSTRIDE + r0 + 8]       = acc[nt][2];
            d_sm[(col + 1) * DSTRIDE + r0 + 8] = acc[nt][3];
        }
    }
    __syncthreads();

    for (int e = tid; e < Cn * 128; e += 256) {
        int k = e >> 7;
        int r = e & 127;
        g_den[(size_t)btc[r] + k * CSTRIDE] = __expf(d_sm[k * DSTRIDE + r]);
    }
}

// ---------------------------------------------------------------------------
// Kernel 3: warp-specialized scan (PROVEN R7 structure). 224 threads.
//  warps 0-1 : denominator (lane v -> state v+1; w1 lane31 handled via tid31),
//              linear beta, renorm every 4 steps via shuffle reduce + bar.sync.
//  warp 2    : numerator, 33 states, shuffle exchange, per-state (m,e),
//              reads tile from SMEM inside the mbarrier pipeline.
//  warps 3-6 : producers; warp w owns ring slot (w-3); cp.async + wait_group 0
//              + mbarrier full/empty handshake (depth-4 ring, empty count 3).
// ---------------------------------------------------------------------------
__global__ __launch_bounds__(224) void k_scan(const int* __restrict__ num_frames,
                                              const int* __restrict__ labels,
                                              const int* __restrict__ num_labels,
                                              float* __restrict__ out) {
    extern __shared__ __align__(16) float tilebuf[];   // 4 * TILE_PAD floats
    __shared__ __align__(16) float beta_sh[2][68];
    __shared__ float maxw[2];
    __shared__ float nm_fin[Un + 1];
    __shared__ int ne_fin[Un + 1];
    __shared__ __align__(8) unsigned long long mbars[8];   // full[0..3], empty[4..7]

    const int b = blockIdx.x;
    const int tid = threadIdx.x;
    const int wid = tid >> 5;
    const int lane = tid & 31;
    const int Tb = num_frames[b];          // in [64, 128]

    uint32_t mb_full[4], mb_empty[4];
#pragma unroll
    for (int s = 0; s < 4; s++) {
        mb_full[s] = smem_u32(&mbars[s]);
        mb_empty[s] = smem_u32(&mbars[4 + s]);
    }
    if (tid == 0) {
#pragma unroll
        for (int s = 0; s < 4; s++) {
            MBAR_INIT(mb_full[s], 32);     // 32 producer-thread arrivals
            MBAR_INIT(mb_empty[s], 3);     // 3 consumer-warp elected arrivals
        }
    }
    // denominator beta init (before the barrier)
    if (wid < 2) {
        beta_sh[0][wid * 32 + lane + 1] = 0.f;
        if (tid == 31) beta_sh[0][0] = 1.f;
    }
    __syncthreads();

    const float* base = g_den + (size_t)(b * Tn) * TILE_PAD;
    int esum = 0;   // only meaningful on den threads; tid0 uses it at the end

    if (wid >= 3) {
        // ---- producer warp: slot p = wid-3, tiles t = p, p+4, ...
        const int p = wid - 3;
        const uint32_t dst0 = smem_u32(tilebuf) + p * TILE_BYTES;
        int eph = 1;                                   // first empty-wait passes
        for (int t = p; t < Tb; t += 4) {
            mbar_wait(mb_empty[p], (uint32_t)eph);
            eph ^= 1;
            const float* src = base + (size_t)t * TILE_PAD;
#pragma unroll 5
            for (int i = lane; i < TILE_PAD / 4; i += 32)
                cp_async16(dst0 + i * 16, src + i * 4);
            CP_COMMIT();
            CP_WAIT0();
            MBAR_ARRIVE(mb_full[p]);
        }
    } else if (wid < 2) {
        // ---- denominator
        const int v = wid * 32 + lane;                 // state v+1
        const bool ex = (tid == 31);                   // also state 0
        const int rowoff = (v + 1) * CSTRIDE;
        float av = 0.f;
        float av0 = ex ? 1.f : 0.f;

        for (int t = 0; t < Tb; t++) {
            const int s = t & 3;
            mbar_wait(mb_full[s], (uint32_t)((t >> 2) & 1));
            const float* Tt = tilebuf + s * TILE_PAD;
            const float* bsh = beta_sh[t & 1];
            const float* rp = Tt + rowoff;

            float s0 = 0.f, s1 = 0.f, s2 = 0.f, s3 = 0.f;
#pragma unroll 8
            for (int c = 0; c < 64; c += 4) {
                s0 += bsh[c]     * rp[c];
                s1 += bsh[c + 1] * rp[c + 1];
                s2 += bsh[c + 2] * rp[c + 2];
                s3 += bsh[c + 3] * rp[c + 3];
            }
            float mv = (s0 + s1) + (s2 + s3) + bsh[64] * rp[64];
            float nv = fmaf(av, Tt[v + 1], mv);
            float nv0 = ex ? av0 * Tt[0] : 0.f;

            __syncwarp();
            if (lane == 0) MBAR_ARRIVE(mb_empty[s]);   // this warp done with tile

            if ((t & 3) == 3) {
                float mx = fmaxf(nv, nv0);
#pragma unroll
                for (int o = 16; o; o >>= 1)
                    mx = fmaxf(mx, __shfl_xor_sync(0xffffffffu, mx, o));
                if (lane == 0) maxw[wid] = mx;
                asm volatile("bar.sync 1, 64;" ::: "memory");
                float gm = fmaxf(maxw[0], maxw[1]);
                int eb = ((__float_as_int(gm) >> 23) & 0xFF) - 127;
                float sc = exp2i(-eb);
                nv *= sc; nv0 *= sc; esum += eb;
            }

            beta_sh[1 - (t & 1)][v + 1] = nv;
            if (ex) beta_sh[1 - (t & 1)][0] = nv0;
            av = nv; av0 = nv0;
            asm volatile("bar.sync 1, 64;" ::: "memory");
        }
    } else {
        // ---- numerator (warp 2): lane j = state j; lane 0 also state 32
        const int* lb = labels + b * Un;
        const int j = lane;
        const int cj = (j == 0) ? 0 : lb[j - 1];
        const int cm = (j >= 2) ? lb[j - 2] : 0;
        const int c32 = lb[31], c31 = lb[30];
        float m = (j == 0) ? 1.f : 0.f;
        int e = (j == 0) ? 0 : EMIN;
        float m2 = 0.f;
        int e2 = EMIN;

        for (int t = 0; t < Tb; t++) {
            const int s = t & 3;
            mbar_wait(mb_full[s], (uint32_t)((t >> 2) & 1));
            const float* Tt = tilebuf + s * TILE_PAD;

            float mp = __shfl_up_sync(0xffffffffu, m, 1);
            int epv = __shfl_up_sync(0xffffffffu, e, 1);
            float m31 = __shfl_sync(0xffffffffu, m, 31);
            int e31 = __shfl_sync(0xffffffffu, e, 31);

            float own = m * Tt[cj];
            float oth = (j > 0) ? mp * Tt[cj * CSTRIDE + cm] : 0.f;
            int epo = (j > 0) ? epv : EMIN;
            int eown = e;
            accum2(own, eown, oth, epo, m, e);

            if (j == 0) {
                float own2 = m2 * Tt[c32];
                float oth2 = m31 * Tt[c32 * CSTRIDE + c31];
                accum2(own2, e2, oth2, e31, m2, e2);
            }

            __syncwarp();
            if (lane == 0) MBAR_ARRIVE(mb_empty[s]);
        }
        nm_fin[j] = m;
        ne_fin[j] = e;
        if (j == 0) { nm_fin[32] = m2; ne_fin[32] = e2; }
    }

    __syncthreads();
    if (tid == 0) {
        const float* bf = beta_sh[Tb & 1];
        float ssum = 0.f;
        for (int c = 0; c < Cn; c++) ssum += bf[c];
        float den = (float)esum * LN2F + __logf(ssum);
        int nl = num_labels[b];
        float num = __logf(nm_fin[nl]) + (float)ne_fin[nl] * LN2F;
        out[b] = den - num;
    }
}

// ---------------------------------------------------------------------------
extern "C" void kernel_launch(void* const* d_in, const int* in_sizes, int n_in,
                              void* d_out, int out_size) {
    const float* frames = (const float*)d_in[0];   // (8,128,512)
    const float* Wf     = (const float*)d_in[1];   // (512,512)
    const float* ce     = (const float*)d_in[2];   // (65,512)
    const float* Wo     = (const float*)d_in[3];   // (512,65)
    const int* nf       = (const int*)d_in[4];     // (8,)
    const int* labels   = (const int*)d_in[5];     // (8,32)
    const int* nl       = (const int*)d_in[6];     // (8,)
    float* out = (float*)d_out;                    // (8,)

    cudaFuncSetAttribute(k_logits, cudaFuncAttributeMaxDynamicSharedMemorySize, DYN_SMEM);
    cudaFuncSetAttribute(k_scan, cudaFuncAttributeMaxDynamicSharedMemorySize, SCAN_SMEM);

    k_prep<<<4, 256>>>(Wo);
    k_proj<<<dim3(Hn / 32, (Bn * Tn) / 64), 128>>>(frames, Wf);
    k_logits<<<NB_LOGITS, 256, DYN_SMEM>>>(ce);
    k_scan<<<Bn, 224, SCAN_SMEM>>>(nf, labels, nl, out);
}